// round 15
// baseline (speedup 1.0000x reference)
#include <cuda_runtime.h>
#include <math.h>

#define BB 512
#define TT 128
#define FF 128
#define HH 256
#define NS 127   // T-1 scan steps

// ---------------- scratch (static device memory; no allocations) ----------------
__device__ float g_vhat[BB*TT*FF];            // values_hat           [b][t][f]  (32MB)
__device__ float g_gamma[BB*TT*HH];           // gamma                [b][t][h]  (64MB)
__device__ float g_zx[NS*BB*4*HH];            // input-gate preact    [t][b][n]  (254MB)
__device__ float g_H[(NS+1)*BB*HH];           // h history, slot0=h0  [t][b][h]  (64MB)
__device__ float g_c[BB*HH];                  // cell state
__device__ float g_invden[NS];
__device__ double g_loss;

__device__ __forceinline__ float sigf(float x){ return 1.f/(1.f+expf(-x)); }

// ---------------- init: h0 = c0 = 0, loss = 0 ----------------
__global__ void k_init()
{
    int i = blockIdx.x*256 + threadIdx.x;
    if (i < BB*HH){ g_c[i] = 0.f; g_H[i] = 0.f; }
    if (i == 0) g_loss = 0.0;
}

// ---------------- per-step loss denominators: 1/(sum(masks[:,t+1])+1e-5) ----------------
__global__ void k_invden(const float* __restrict__ masks)
{
    int t = blockIdx.x;              // 0..126, uses masks at time t+1
    float s = 0.f;
    for (int i = threadIdx.x; i < BB*FF; i += 256){
        int b = i >> 7, f = i & 127;
        s += masks[(b*TT + (t+1))*FF + f];
    }
    __shared__ float red[256];
    red[threadIdx.x] = s; __syncthreads();
    for (int off = 128; off > 0; off >>= 1){
        if (threadIdx.x < off) red[threadIdx.x] += red[threadIdx.x+off];
        __syncthreads();
    }
    if (threadIdx.x == 0) g_invden[t] = 1.f/(red[0] + 1e-5f);
}

// ---------------- values_hat: feature + temporal regression fused ----------------
// one block per batch b; V, feat_W, temp_W all resident in smem (203KB)
__global__ __launch_bounds__(256) void k_vhat(
    const float* __restrict__ values, const float* __restrict__ masks,
    const float* __restrict__ featW,  const float* __restrict__ featb,
    const float* __restrict__ tempW,  const float* __restrict__ tempb)
{
    extern __shared__ float sm[];
    float* Vs = sm;                // [128][132]
    float* Wf = sm + 128*132;      // [128][132]
    float* Wt = sm + 2*128*132;    // [128][132]
    const int b = blockIdx.x, tid = threadIdx.x;
    const float4* v4 = (const float4*)(values + b*TT*FF);
    const float4* f4 = (const float4*)featW;
    const float4* t4 = (const float4*)tempW;
#pragma unroll
    for (int q = 0; q < 16; q++){
        int i4 = tid + q*256;
        int row = i4 >> 5, c4 = i4 & 31;
        *(float4*)&Vs[row*132 + c4*4] = v4[i4];
        *(float4*)&Wf[row*132 + c4*4] = f4[i4];
        *(float4*)&Wt[row*132 + c4*4] = t4[i4];
    }
    __syncthreads();
    const int tx = tid & 15, ty = tid >> 4;
    float acc[8][8];
#pragma unroll
    for (int i=0;i<8;i++)
#pragma unroll
        for (int j=0;j<8;j++) acc[i][j] = 0.f;

    // pass 1: acc[t][g] += V[t][k] * featW[g][k]
    for (int k0 = 0; k0 < 128; k0 += 4){
        float4 a[8], w[8];
#pragma unroll
        for (int i=0;i<8;i++) a[i] = *(const float4*)&Vs[(ty+16*i)*132 + k0];
#pragma unroll
        for (int j=0;j<8;j++) w[j] = *(const float4*)&Wf[(tx+16*j)*132 + k0];
#pragma unroll
        for (int i=0;i<8;i++)
#pragma unroll
            for (int j=0;j<8;j++)
                acc[i][j] += a[i].x*w[j].x + a[i].y*w[j].y + a[i].z*w[j].z + a[i].w*w[j].w;
    }
    // pass 2: acc[t][g] += tempW[t][s] * V[s][g]
    for (int k0 = 0; k0 < 128; k0 += 4){
        float4 a[8];
#pragma unroll
        for (int i=0;i<8;i++) a[i] = *(const float4*)&Wt[(ty+16*i)*132 + k0];
#pragma unroll
        for (int kk=0;kk<4;kk++){
            float vg[8];
#pragma unroll
            for (int j=0;j<8;j++) vg[j] = Vs[(k0+kk)*132 + tx + 16*j];
#pragma unroll
            for (int i=0;i<8;i++){
                float av = (kk==0)?a[i].x:(kk==1)?a[i].y:(kk==2)?a[i].z:a[i].w;
#pragma unroll
                for (int j=0;j<8;j++) acc[i][j] += av * vg[j];
            }
        }
    }
    const float* mrow = masks + b*TT*FF;
#pragma unroll
    for (int i=0;i<8;i++){
        int t = ty + 16*i;
        float tb  = tempb[t];
        float wtd = Wt[t*132 + t];
#pragma unroll
        for (int j=0;j<8;j++){
            int g = tx + 16*j;
            float v  = Vs[t*132 + g];
            float vh = acc[i][j] - v*(Wf[g*132 + g] + wtd) + featb[g] + tb;
            float m  = mrow[t*FF + g];
            g_vhat[(b*TT + t)*FF + g] = v*m + vh*(1.f - m);
        }
    }
}

// ---------------- gamma = exp(-|deltas @ decay_W^T + b|) ----------------
// tile: 128 rows x 64 h, K=128 resident
__global__ __launch_bounds__(256) void k_gamma(
    const float* __restrict__ deltas, const float* __restrict__ decayW,
    const float* __restrict__ decayb)
{
    extern __shared__ float sm[];
    float* As = sm;               // [128][132]
    float* Bs = sm + 128*132;     // [64][132]
    const int r0 = blockIdx.x*128, h0 = blockIdx.y*64, tid = threadIdx.x;
    const float4* a4 = (const float4*)(deltas + r0*FF);
#pragma unroll
    for (int q=0;q<16;q++){
        int i4 = tid + q*256;
        int row = i4 >> 5, c4 = i4 & 31;
        *(float4*)&As[row*132 + c4*4] = a4[i4];
    }
    const float4* b4 = (const float4*)(decayW + h0*FF);
#pragma unroll
    for (int q=0;q<8;q++){
        int i4 = tid + q*256;
        int row = i4 >> 5, c4 = i4 & 31;
        *(float4*)&Bs[row*132 + c4*4] = b4[i4];
    }
    __syncthreads();
    const int tx = tid & 15, ty = tid >> 4;
    float acc[8][4];
#pragma unroll
    for (int i=0;i<8;i++)
#pragma unroll
        for (int q=0;q<4;q++) acc[i][q]=0.f;
    for (int k0=0;k0<128;k0+=4){
        float4 a[8], w[4];
#pragma unroll
        for (int i=0;i<8;i++) a[i] = *(const float4*)&As[(ty+16*i)*132 + k0];
#pragma unroll
        for (int q=0;q<4;q++) w[q] = *(const float4*)&Bs[(tx+16*q)*132 + k0];
#pragma unroll
        for (int i=0;i<8;i++)
#pragma unroll
            for (int q=0;q<4;q++)
                acc[i][q] += a[i].x*w[q].x + a[i].y*w[q].y + a[i].z*w[q].z + a[i].w*w[q].w;
    }
#pragma unroll
    for (int i=0;i<8;i++){
        int r = r0 + ty + 16*i;
#pragma unroll
        for (int q=0;q<4;q++){
            int h = h0 + tx + 16*q;
            g_gamma[r*HH + h] = expf(-fabsf(acc[i][q] + decayb[h]));
        }
    }
}

// ---------------- zx = [values_hat, masks] @ W_ih^T + b_ih + b_hh (all steps at once) ----------------
// M=65024 (r=t*512+b), N=1024, K=256 (2 chunks of 128)
__global__ __launch_bounds__(256) void k_zx(
    const float* __restrict__ masks, const float* __restrict__ Wih,
    const float* __restrict__ bih,   const float* __restrict__ bhh)
{
    extern __shared__ float sm[];
    float* As = sm;               // [128][132]
    float* Bs = sm + 128*132;     // [128][132]
    const int r0 = blockIdx.x*128, n0 = blockIdx.y*128, tid = threadIdx.x;
    const int tx = tid & 15, ty = tid >> 4;
    float acc[8][8];
#pragma unroll
    for (int i=0;i<8;i++)
#pragma unroll
        for (int j=0;j<8;j++) acc[i][j]=0.f;

    for (int kc = 0; kc < 2; kc++){
#pragma unroll
        for (int q=0;q<16;q++){
            int i4 = tid + q*256;
            int row = i4 >> 5, c4 = i4 & 31;
            int r = r0 + row;
            int t = r >> 9, b = r & 511;
            const float* src = (kc==0) ? g_vhat : masks;
            *(float4*)&As[row*132 + c4*4] = *(const float4*)&src[(b*TT + t)*FF + c4*4];
            *(float4*)&Bs[row*132 + c4*4] = *(const float4*)&Wih[(n0+row)*256 + kc*128 + c4*4];
        }
        __syncthreads();
        for (int k0=0;k0<128;k0+=4){
            float4 a[8], w[8];
#pragma unroll
            for (int i=0;i<8;i++) a[i] = *(const float4*)&As[(ty+16*i)*132 + k0];
#pragma unroll
            for (int j=0;j<8;j++) w[j] = *(const float4*)&Bs[(tx+16*j)*132 + k0];
#pragma unroll
            for (int i=0;i<8;i++)
#pragma unroll
                for (int j=0;j<8;j++)
                    acc[i][j] += a[i].x*w[j].x + a[i].y*w[j].y + a[i].z*w[j].z + a[i].w*w[j].w;
        }
        __syncthreads();
    }
#pragma unroll
    for (int i=0;i<8;i++){
        int r = r0 + ty + 16*i;
#pragma unroll
        for (int j=0;j<8;j++){
            int n = n0 + tx + 16*j;
            g_zx[r*1024 + n] = acc[i][j] + bih[n] + bhh[n];
        }
    }
}

// ---------------- one LSTM scan step: h' , c' from h*gamma, zx[t], W_hh ----------------
// grid (16,8): b-tile 32, j-tile 32 (x4 gates). 128 threads, 166KB smem.
__global__ __launch_bounds__(128) void k_step(const float* __restrict__ Whh, int t)
{
    extern __shared__ float sm[];
    float* hs = sm;              // [32][260]  decayed h
    float* ws = sm + 32*260;     // [128][260] 4 gates x 32 j rows of W_hh
    const int b0 = blockIdx.x*32, j0 = blockIdx.y*32, tid = threadIdx.x;
#pragma unroll
    for (int q=0;q<16;q++){
        int i4 = tid + q*128;
        int row = i4 >> 6, c4 = i4 & 63;
        int b = b0 + row;
        float4 hv = *(const float4*)&g_H[(t*512 + b)*256 + c4*4];
        float4 gv = *(const float4*)&g_gamma[(b*TT + t)*HH + c4*4];
        float4 o; o.x=hv.x*gv.x; o.y=hv.y*gv.y; o.z=hv.z*gv.z; o.w=hv.w*gv.w;
        *(float4*)&hs[row*260 + c4*4] = o;
    }
#pragma unroll
    for (int q=0;q<64;q++){
        int i4 = tid + q*128;
        int row = i4 >> 6, c4 = i4 & 63;
        int gate = row >> 5, jj = row & 31;
        *(float4*)&ws[row*260 + c4*4] = *(const float4*)&Whh[(gate*256 + j0 + jj)*256 + c4*4];
    }
    __syncthreads();
    const int tx = tid & 15, ty = tid >> 4;   // ty 0..7
    float acc[4][2][4];
#pragma unroll
    for (int i=0;i<4;i++)
#pragma unroll
        for (int q=0;q<2;q++)
#pragma unroll
            for (int g=0;g<4;g++) acc[i][q][g]=0.f;

    for (int k0=0;k0<256;k0+=4){
        float4 a[4];
#pragma unroll
        for (int i=0;i<4;i++) a[i] = *(const float4*)&hs[(ty*4+i)*260 + k0];
#pragma unroll
        for (int q=0;q<2;q++)
#pragma unroll
            for (int g=0;g<4;g++){
                float4 w = *(const float4*)&ws[(g*32 + tx + 16*q)*260 + k0];
#pragma unroll
                for (int i=0;i<4;i++)
                    acc[i][q][g] += a[i].x*w.x + a[i].y*w.y + a[i].z*w.z + a[i].w*w.w;
            }
    }
#pragma unroll
    for (int i=0;i<4;i++){
        int b = b0 + ty*4 + i;
        const float* zr = g_zx + (t*512 + b)*1024;
#pragma unroll
        for (int q=0;q<2;q++){
            int j = j0 + tx + 16*q;
            float zi = acc[i][q][0] + zr[j];
            float zf = acc[i][q][1] + zr[256 + j];
            float zg = acc[i][q][2] + zr[512 + j];
            float zo = acc[i][q][3] + zr[768 + j];
            float ii = sigf(zi), ff = sigf(zf), gg = tanhf(zg), oo = sigf(zo);
            float c = ff * g_c[b*256 + j] + ii*gg;
            g_c[b*256 + j] = c;
            g_H[((t+1)*512 + b)*256 + j] = oo * tanhf(c);
        }
    }
}

// ---------------- all output projections + masked L1 loss in one GEMM ----------------
// M=65024 rows (r=t*512+b, uses g_H[t+1]), N=128, K=256; 64-row tiles stay within one t
__global__ __launch_bounds__(256) void k_loss(
    const float* __restrict__ values, const float* __restrict__ masks,
    const float* __restrict__ outW,   const float* __restrict__ outb)
{
    extern __shared__ float sm[];
    float* As = sm;              // [64][260]
    float* Bs = sm + 64*260;     // [128][260]
    const int r0 = blockIdx.x*64;
    const int t = r0 >> 9;
    const int tid = threadIdx.x;
#pragma unroll
    for (int q=0;q<16;q++){
        int i4 = tid + q*256;
        int row = i4 >> 6, c4 = i4 & 63;
        int r = r0 + row, b = r & 511;
        *(float4*)&As[row*260 + c4*4] = *(const float4*)&g_H[((t+1)*512 + b)*256 + c4*4];
    }
#pragma unroll
    for (int q=0;q<32;q++){
        int i4 = tid + q*256;
        int row = i4 >> 6, c4 = i4 & 63;
        *(float4*)&Bs[row*260 + c4*4] = *(const float4*)&outW[row*256 + c4*4];
    }
    __syncthreads();
    const int tx = tid & 15, ty = tid >> 4;
    float acc[4][8];
#pragma unroll
    for (int i=0;i<4;i++)
#pragma unroll
        for (int j=0;j<8;j++) acc[i][j]=0.f;
    for (int k0=0;k0<256;k0+=4){
        float4 a[4], w[8];
#pragma unroll
        for (int i=0;i<4;i++) a[i] = *(const float4*)&As[(ty+16*i)*260 + k0];
#pragma unroll
        for (int j=0;j<8;j++) w[j] = *(const float4*)&Bs[(tx+16*j)*260 + k0];
#pragma unroll
        for (int i=0;i<4;i++)
#pragma unroll
            for (int j=0;j<8;j++)
                acc[i][j] += a[i].x*w[j].x + a[i].y*w[j].y + a[i].z*w[j].z + a[i].w*w[j].w;
    }
    float local = 0.f;
#pragma unroll
    for (int i=0;i<4;i++){
        int r = r0 + ty + 16*i, b = r & 511;
#pragma unroll
        for (int j=0;j<8;j++){
            int f = tx + 16*j;
            float out = acc[i][j] + outb[f];
            int gi = (b*TT + (t+1))*FF + f;
            local += fabsf(values[gi] - out) * masks[gi];
        }
    }
    local *= g_invden[t];
    __syncthreads();               // done reading smem; reuse for reduction
    As[tid] = local;
    __syncthreads();
    for (int off = 128; off > 0; off >>= 1){
        if (tid < off) As[tid] += As[tid+off];
        __syncthreads();
    }
    if (tid == 0) atomicAdd(&g_loss, (double)As[0]);
}

// ---------------- gather outputs: [h_final | c_final | loss] ----------------
__global__ void k_final(float* __restrict__ out)
{
    int i = blockIdx.x*256 + threadIdx.x;
    if (i < BB*HH)            out[i] = g_H[NS*BB*HH + i];
    else if (i < 2*BB*HH)     out[i] = g_c[i - BB*HH];
    else if (i == 2*BB*HH)    out[i] = (float)g_loss;
}

// ---------------- launch ----------------
extern "C" void kernel_launch(void* const* d_in, const int* in_sizes, int n_in,
                              void* d_out, int out_size)
{
    const float* values = (const float*)d_in[0];
    const float* masks  = (const float*)d_in[1];
    const float* deltas = (const float*)d_in[2];
    const float* featW  = (const float*)d_in[3];
    const float* featb  = (const float*)d_in[4];
    const float* tempW  = (const float*)d_in[5];
    const float* tempb  = (const float*)d_in[6];
    const float* decayW = (const float*)d_in[7];
    const float* decayb = (const float*)d_in[8];
    const float* Wih    = (const float*)d_in[9];
    const float* Whh    = (const float*)d_in[10];
    const float* bih    = (const float*)d_in[11];
    const float* bhh    = (const float*)d_in[12];
    const float* outW   = (const float*)d_in[13];
    const float* outb   = (const float*)d_in[14];

    const int SM_VHAT  = 3*128*132*4;        // 202752
    const int SM_GAMMA = (128+64)*132*4;     // 101376
    const int SM_ZX    = 2*128*132*4;        // 135168
    const int SM_STEP  = (32+128)*260*4;     // 166400
    const int SM_LOSS  = (64+128)*260*4;     // 199680

    cudaFuncSetAttribute(k_vhat,  cudaFuncAttributeMaxDynamicSharedMemorySize, SM_VHAT);
    cudaFuncSetAttribute(k_gamma, cudaFuncAttributeMaxDynamicSharedMemorySize, SM_GAMMA);
    cudaFuncSetAttribute(k_zx,    cudaFuncAttributeMaxDynamicSharedMemorySize, SM_ZX);
    cudaFuncSetAttribute(k_step,  cudaFuncAttributeMaxDynamicSharedMemorySize, SM_STEP);
    cudaFuncSetAttribute(k_loss,  cudaFuncAttributeMaxDynamicSharedMemorySize, SM_LOSS);

    k_init<<<512, 256>>>();
    k_invden<<<NS, 256>>>(masks);
    k_vhat<<<BB, 256, SM_VHAT>>>(values, masks, featW, featb, tempW, tempb);
    k_gamma<<<dim3(BB*TT/128, HH/64), 256, SM_GAMMA>>>(deltas, decayW, decayb);
    k_zx<<<dim3(NS*BB/128, 4*HH/128), 256, SM_ZX>>>(masks, Wih, bih, bhh);
    for (int t = 0; t < NS; t++)
        k_step<<<dim3(16, 8), 128, SM_STEP>>>(Whh, t);
    k_loss<<<NS*BB/64, 256, SM_LOSS>>>(values, masks, outW, outb);
    k_final<<<(2*BB*HH + 1 + 255)/256, 256>>>((float*)d_out);
}

// round 16
// speedup vs baseline: 1.7703x; 1.7703x over previous
#include <cuda_runtime.h>
#include <math.h>
#include <stdint.h>

#define BB 512
#define TT 128
#define FF 128
#define HH 256
#define NS 127   // T-1 scan steps

// ---------------- scratch (static device memory; no allocations) ----------------
__device__ float g_vhat[BB*TT*FF];            // values_hat           [b][t][f]
__device__ float g_gamma[BB*TT*HH];           // gamma                [b*T+t][h]
__device__ float g_zx[NS*BB*4*HH];            // input-gate preact    [t][b][n]
__device__ float g_H[(NS+1)*BB*HH];           // h history, slot0=h0  [t][b][h]
__device__ float g_c[BB*HH];                  // cell state
__device__ float g_invden[NS];
__device__ double g_loss;

__device__ __forceinline__ float sigf(float x){ return 1.f/(1.f+expf(-x)); }

__device__ __forceinline__ uint32_t f2tf(float x){
    uint32_t r; asm("cvt.rna.tf32.f32 %0, %1;" : "=r"(r) : "f"(x)); return r;
}
// D += A(16x8,row) * B(8x8,col), tf32 in, fp32 accum
__device__ __forceinline__ void mma8(float* d,
    uint32_t a0, uint32_t a1, uint32_t a2, uint32_t a3,
    uint32_t b0, uint32_t b1)
{
    asm volatile("mma.sync.aligned.m16n8k8.row.col.f32.tf32.tf32.f32 "
        "{%0,%1,%2,%3}, {%4,%5,%6,%7}, {%8,%9}, {%0,%1,%2,%3};"
        : "+f"(d[0]), "+f"(d[1]), "+f"(d[2]), "+f"(d[3])
        : "r"(a0), "r"(a1), "r"(a2), "r"(a3), "r"(b0), "r"(b1));
}

#define LDK 260   // K=256 pad  (260 % 32 == 4 -> conflict-free fragment LDS)
#define LDK1 132  // K=128 pad

// ---------------- init: h0 = c0 = 0, loss = 0 ----------------
__global__ void k_init()
{
    int i = blockIdx.x*256 + threadIdx.x;
    if (i < BB*HH){ g_c[i] = 0.f; g_H[i] = 0.f; }
    if (i == 0) g_loss = 0.0;
}

// ---------------- per-step loss denominators: 1/(sum(masks[:,t+1])+1e-5) ----------------
__global__ void k_invden(const float* __restrict__ masks)
{
    int t = blockIdx.x;              // 0..126, uses masks at time t+1
    float s = 0.f;
    for (int i = threadIdx.x; i < BB*FF; i += 256){
        int b = i >> 7, f = i & 127;
        s += masks[(b*TT + (t+1))*FF + f];
    }
    __shared__ float red[256];
    red[threadIdx.x] = s; __syncthreads();
    for (int off = 128; off > 0; off >>= 1){
        if (threadIdx.x < off) red[threadIdx.x] += red[threadIdx.x+off];
        __syncthreads();
    }
    if (threadIdx.x == 0) g_invden[t] = 1.f/(red[0] + 1e-5f);
}

// ---------------- values_hat: feature + temporal regression fused (exact fp32) ----------------
__global__ __launch_bounds__(256) void k_vhat(
    const float* __restrict__ values, const float* __restrict__ masks,
    const float* __restrict__ featW,  const float* __restrict__ featb,
    const float* __restrict__ tempW,  const float* __restrict__ tempb)
{
    extern __shared__ float sm[];
    float* Vs = sm;                // [128][132]
    float* Wf = sm + 128*132;      // [128][132]
    float* Wt = sm + 2*128*132;    // [128][132]
    const int b = blockIdx.x, tid = threadIdx.x;
    const float4* v4 = (const float4*)(values + b*TT*FF);
    const float4* f4 = (const float4*)featW;
    const float4* t4 = (const float4*)tempW;
#pragma unroll
    for (int q = 0; q < 16; q++){
        int i4 = tid + q*256;
        int row = i4 >> 5, c4 = i4 & 31;
        *(float4*)&Vs[row*132 + c4*4] = v4[i4];
        *(float4*)&Wf[row*132 + c4*4] = f4[i4];
        *(float4*)&Wt[row*132 + c4*4] = t4[i4];
    }
    __syncthreads();
    const int tx = tid & 15, ty = tid >> 4;
    float acc[8][8];
#pragma unroll
    for (int i=0;i<8;i++)
#pragma unroll
        for (int j=0;j<8;j++) acc[i][j] = 0.f;

    for (int k0 = 0; k0 < 128; k0 += 4){
        float4 a[8], w[8];
#pragma unroll
        for (int i=0;i<8;i++) a[i] = *(const float4*)&Vs[(ty+16*i)*132 + k0];
#pragma unroll
        for (int j=0;j<8;j++) w[j] = *(const float4*)&Wf[(tx+16*j)*132 + k0];
#pragma unroll
        for (int i=0;i<8;i++)
#pragma unroll
            for (int j=0;j<8;j++)
                acc[i][j] += a[i].x*w[j].x + a[i].y*w[j].y + a[i].z*w[j].z + a[i].w*w[j].w;
    }
    for (int k0 = 0; k0 < 128; k0 += 4){
        float4 a[8];
#pragma unroll
        for (int i=0;i<8;i++) a[i] = *(const float4*)&Wt[(ty+16*i)*132 + k0];
#pragma unroll
        for (int kk=0;kk<4;kk++){
            float vg[8];
#pragma unroll
            for (int j=0;j<8;j++) vg[j] = Vs[(k0+kk)*132 + tx + 16*j];
#pragma unroll
            for (int i=0;i<8;i++){
                float av = (kk==0)?a[i].x:(kk==1)?a[i].y:(kk==2)?a[i].z:a[i].w;
#pragma unroll
                for (int j=0;j<8;j++) acc[i][j] += av * vg[j];
            }
        }
    }
    const float* mrow = masks + b*TT*FF;
#pragma unroll
    for (int i=0;i<8;i++){
        int t = ty + 16*i;
        float tb  = tempb[t];
        float wtd = Wt[t*132 + t];
#pragma unroll
        for (int j=0;j<8;j++){
            int g = tx + 16*j;
            float v  = Vs[t*132 + g];
            float vh = acc[i][j] - v*(Wf[g*132 + g] + wtd) + featb[g] + tb;
            float m  = mrow[t*FF + g];
            g_vhat[(b*TT + t)*FF + g] = v*m + vh*(1.f - m);
        }
    }
}

// ---------------- gamma = exp(-|deltas @ decay_W^T + b|)  (TF32 mma) ----------------
// tile 128 rows x 64 h, K=128 resident; 8 warps of 32x32 (wm 0..3, wn 0..1)
__global__ __launch_bounds__(256) void k_gamma_tc(
    const float* __restrict__ deltas, const float* __restrict__ decayW,
    const float* __restrict__ decayb)
{
    extern __shared__ uint32_t smu[];
    uint32_t* As = smu;               // [128][132]
    uint32_t* Bs = smu + 128*LDK1;    // [64][132]
    __shared__ float db[64];
    const int r0 = blockIdx.x*128, h0 = blockIdx.y*64, tid = threadIdx.x;
    if (tid < 64) db[tid] = decayb[h0 + tid];
#pragma unroll
    for (int q=0;q<16;q++){
        int i4 = tid + q*256;                // 0..4095
        int row = i4 >> 5, c4 = i4 & 31;
        float4 v = *(const float4*)&deltas[(r0+row)*FF + c4*4];
        uint32_t* d = &As[row*LDK1 + c4*4];
        d[0]=f2tf(v.x); d[1]=f2tf(v.y); d[2]=f2tf(v.z); d[3]=f2tf(v.w);
    }
#pragma unroll
    for (int q=0;q<8;q++){
        int i4 = tid + q*256;                // 0..2047
        int row = i4 >> 5, c4 = i4 & 31;
        float4 v = *(const float4*)&decayW[(h0+row)*FF + c4*4];
        uint32_t* d = &Bs[row*LDK1 + c4*4];
        d[0]=f2tf(v.x); d[1]=f2tf(v.y); d[2]=f2tf(v.z); d[3]=f2tf(v.w);
    }
    __syncthreads();
    const int wid = tid>>5, lane = tid&31;
    const int wm = wid & 3, wn = wid >> 2;
    const int g = lane>>2, tg = lane&3;
    float acc[2][4][4];
#pragma unroll
    for (int mi=0;mi<2;mi++)
#pragma unroll
        for (int ni=0;ni<4;ni++)
#pragma unroll
            for (int q=0;q<4;q++) acc[mi][ni][q]=0.f;
    const uint32_t* Ab = &As[(wm*32)*LDK1];
    const uint32_t* Bb = &Bs[(wn*32)*LDK1];
    for (int k0=0;k0<128;k0+=8){
        uint32_t a[2][4], b[4][2];
#pragma unroll
        for (int mi=0;mi<2;mi++){
            const uint32_t* p  = Ab + (mi*16+g)*LDK1 + k0 + tg;
            const uint32_t* p2 = p + 8*LDK1;
            a[mi][0]=p[0]; a[mi][2]=p[4]; a[mi][1]=p2[0]; a[mi][3]=p2[4];
        }
#pragma unroll
        for (int ni=0;ni<4;ni++){
            const uint32_t* p = Bb + (ni*8+g)*LDK1 + k0 + tg;
            b[ni][0]=p[0]; b[ni][1]=p[4];
        }
#pragma unroll
        for (int mi=0;mi<2;mi++)
#pragma unroll
            for (int ni=0;ni<4;ni++)
                mma8(acc[mi][ni], a[mi][0],a[mi][1],a[mi][2],a[mi][3], b[ni][0],b[ni][1]);
    }
#pragma unroll
    for (int mi=0;mi<2;mi++){
        int r = r0 + wm*32 + mi*16 + g;
#pragma unroll
        for (int ni=0;ni<4;ni++){
            int nl = wn*32 + ni*8 + 2*tg;
            float2 v0 = { expf(-fabsf(acc[mi][ni][0] + db[nl])),
                          expf(-fabsf(acc[mi][ni][1] + db[nl+1])) };
            *(float2*)&g_gamma[r*HH + h0 + nl] = v0;
            float2 v1 = { expf(-fabsf(acc[mi][ni][2] + db[nl])),
                          expf(-fabsf(acc[mi][ni][3] + db[nl+1])) };
            *(float2*)&g_gamma[(r+8)*HH + h0 + nl] = v1;
        }
    }
}

// ---------------- zx = [values_hat, masks] @ W_ih^T + b_ih + b_hh  (TF32 mma) ----------------
// M=65024 (r=t*512+b), N=1024, K=256; block tile 128x64, 8 warps of 32x32 (wm 0..3, wn 0..1)
__global__ __launch_bounds__(256) void k_zx_tc(
    const float* __restrict__ masks, const float* __restrict__ Wih,
    const float* __restrict__ bih,   const float* __restrict__ bhh)
{
    extern __shared__ uint32_t smu[];
    uint32_t* As = smu;              // [128][260]
    uint32_t* Bs = smu + 128*LDK;    // [64][260]
    __shared__ float bb[64];
    const int r0 = blockIdx.x*128, n0 = blockIdx.y*64, tid = threadIdx.x;
    if (tid < 64) bb[tid] = bih[n0+tid] + bhh[n0+tid];
#pragma unroll
    for (int q = 0; q < 32; q++){
        int i4 = tid + q*256;        // 0..8191
        int row = i4 >> 6, c4 = i4 & 63;
        int r = r0 + row, t = r >> 9, b = r & 511;
        int k = c4*4;
        const float* src = (k < 128) ? &g_vhat[(b*TT+t)*FF + k]
                                     : &masks[(b*TT+t)*FF + (k-128)];
        float4 v = *(const float4*)src;
        uint32_t* d = &As[row*LDK + k];
        d[0]=f2tf(v.x); d[1]=f2tf(v.y); d[2]=f2tf(v.z); d[3]=f2tf(v.w);
    }
#pragma unroll
    for (int q = 0; q < 16; q++){
        int i4 = tid + q*256;        // 0..4095
        int row = i4 >> 6, c4 = i4 & 63;
        float4 v = *(const float4*)&Wih[(n0+row)*256 + c4*4];
        uint32_t* d = &Bs[row*LDK + c4*4];
        d[0]=f2tf(v.x); d[1]=f2tf(v.y); d[2]=f2tf(v.z); d[3]=f2tf(v.w);
    }
    __syncthreads();
    const int wid = tid>>5, lane = tid&31;
    const int wm = wid & 3, wn = wid >> 2;
    const int g = lane>>2, tg = lane&3;
    float acc[2][4][4];
#pragma unroll
    for (int mi=0;mi<2;mi++)
#pragma unroll
        for (int ni=0;ni<4;ni++)
#pragma unroll
            for (int q=0;q<4;q++) acc[mi][ni][q]=0.f;
    const uint32_t* Ab = &As[(wm*32)*LDK];
    const uint32_t* Bb = &Bs[(wn*32)*LDK];
    for (int k0 = 0; k0 < 256; k0 += 8){
        uint32_t a[2][4], b[4][2];
#pragma unroll
        for (int mi=0;mi<2;mi++){
            const uint32_t* p  = Ab + (mi*16+g)*LDK + k0 + tg;
            const uint32_t* p2 = p + 8*LDK;
            a[mi][0]=p[0]; a[mi][2]=p[4]; a[mi][1]=p2[0]; a[mi][3]=p2[4];
        }
#pragma unroll
        for (int ni=0;ni<4;ni++){
            const uint32_t* p = Bb + (ni*8+g)*LDK + k0 + tg;
            b[ni][0]=p[0]; b[ni][1]=p[4];
        }
#pragma unroll
        for (int mi=0;mi<2;mi++)
#pragma unroll
            for (int ni=0;ni<4;ni++)
                mma8(acc[mi][ni], a[mi][0],a[mi][1],a[mi][2],a[mi][3], b[ni][0],b[ni][1]);
    }
#pragma unroll
    for (int mi=0;mi<2;mi++){
        int r = r0 + wm*32 + mi*16 + g;
#pragma unroll
        for (int ni=0;ni<4;ni++){
            int nl = wn*32 + ni*8 + 2*tg;
            float2 v0 = { acc[mi][ni][0] + bb[nl], acc[mi][ni][1] + bb[nl+1] };
            *(float2*)&g_zx[r*1024 + n0 + nl] = v0;
            float2 v1 = { acc[mi][ni][2] + bb[nl], acc[mi][ni][3] + bb[nl+1] };
            *(float2*)&g_zx[(r+8)*1024 + n0 + nl] = v1;
        }
    }
}

// ---------------- one LSTM scan step (TF32 mma) ----------------
// block tile 32(b) x 64(n = 4 gates x 16 j); 4 warps, warp wn owns gate wn (32x16).
// grid (16,16)=256 blocks, 128 threads.
__global__ __launch_bounds__(128) void k_step_tc(const float* __restrict__ Whh, int t)
{
    extern __shared__ uint32_t smu[];
    uint32_t* As = smu;             // [32][260]  decayed h (tf32)
    uint32_t* Bs = smu + 32*LDK;    // [64][260]  Whh rows: 4 gates x 16 j
    const int b0 = blockIdx.x*32, j0 = blockIdx.y*16, tid = threadIdx.x;
#pragma unroll
    for (int q = 0; q < 16; q++){
        int i4 = tid + q*128;        // 0..2047
        int row = i4 >> 6, c4 = i4 & 63;
        int b = b0 + row;
        float4 hv = *(const float4*)&g_H[(t*512 + b)*256 + c4*4];
        float4 gv = *(const float4*)&g_gamma[(b*TT + t)*HH + c4*4];
        uint32_t* d = &As[row*LDK + c4*4];
        d[0]=f2tf(hv.x*gv.x); d[1]=f2tf(hv.y*gv.y);
        d[2]=f2tf(hv.z*gv.z); d[3]=f2tf(hv.w*gv.w);
    }
#pragma unroll
    for (int q = 0; q < 32; q++){
        int i4 = tid + q*128;        // 0..4095
        int row = i4 >> 6, c4 = i4 & 63;
        int gate = row >> 4, jj = row & 15;
        float4 v = *(const float4*)&Whh[(gate*256 + j0 + jj)*256 + c4*4];
        uint32_t* d = &Bs[row*LDK + c4*4];
        d[0]=f2tf(v.x); d[1]=f2tf(v.y); d[2]=f2tf(v.z); d[3]=f2tf(v.w);
    }
    __syncthreads();
    const int wid = tid>>5, lane = tid&31;
    const int wn = wid;              // gate index
    const int g = lane>>2, tg = lane&3;
    float acc[2][2][4];
#pragma unroll
    for (int mi=0;mi<2;mi++)
#pragma unroll
        for (int ni=0;ni<2;ni++)
#pragma unroll
            for (int q=0;q<4;q++) acc[mi][ni][q]=0.f;
    const uint32_t* Bb = &Bs[(wn*16)*LDK];
    for (int k0 = 0; k0 < 256; k0 += 8){
        uint32_t a[2][4], b[2][2];
#pragma unroll
        for (int mi=0;mi<2;mi++){
            const uint32_t* p  = &As[(mi*16+g)*LDK + k0 + tg];
            const uint32_t* p2 = p + 8*LDK;
            a[mi][0]=p[0]; a[mi][2]=p[4]; a[mi][1]=p2[0]; a[mi][3]=p2[4];
        }
#pragma unroll
        for (int ni=0;ni<2;ni++){
            const uint32_t* p = Bb + (ni*8+g)*LDK + k0 + tg;
            b[ni][0]=p[0]; b[ni][1]=p[4];
        }
#pragma unroll
        for (int mi=0;mi<2;mi++)
#pragma unroll
            for (int ni=0;ni<2;ni++)
                mma8(acc[mi][ni], a[mi][0],a[mi][1],a[mi][2],a[mi][3], b[ni][0],b[ni][1]);
    }
    __syncthreads();                     // everyone done reading As/Bs
    float* Zs = (float*)smu;             // reuse As region: [32][260] floats
#pragma unroll
    for (int mi=0;mi<2;mi++){
        int rr = mi*16 + g;
#pragma unroll
        for (int ni=0;ni<2;ni++){
            int cc = wn*16 + ni*8 + 2*tg;
            Zs[rr*LDK + cc]     = acc[mi][ni][0];
            Zs[rr*LDK + cc + 1] = acc[mi][ni][1];
            Zs[(rr+8)*LDK + cc]     = acc[mi][ni][2];
            Zs[(rr+8)*LDK + cc + 1] = acc[mi][ni][3];
        }
    }
    __syncthreads();
    // gate fusion: 32 b x 16 j = 512 pairs / 128 threads
#pragma unroll
    for (int q = 0; q < 4; q++){
        int idx = tid + q*128;       // 0..511
        int bl = idx >> 4, jj = idx & 15;
        int b = b0 + bl, j = j0 + jj;
        const float* zr = g_zx + (t*512 + b)*1024;
        float zi = Zs[bl*LDK + 0*16 + jj] + zr[j];
        float zf = Zs[bl*LDK + 1*16 + jj] + zr[256 + j];
        float zg = Zs[bl*LDK + 2*16 + jj] + zr[512 + j];
        float zo = Zs[bl*LDK + 3*16 + jj] + zr[768 + j];
        float ii = sigf(zi), ff = sigf(zf), gg = tanhf(zg), oo = sigf(zo);
        float c = ff * g_c[b*256 + j] + ii*gg;
        g_c[b*256 + j] = c;
        g_H[((t+1)*512 + b)*256 + j] = oo * tanhf(c);
    }
}

// ---------------- output projection + masked L1 loss (TF32 mma) ----------------
// block tile 64(r, within one t) x 128(f); 8 warps of 32x32 (wm 0..1, wn 0..3)
__global__ __launch_bounds__(256) void k_loss_tc(
    const float* __restrict__ values, const float* __restrict__ masks,
    const float* __restrict__ outW,   const float* __restrict__ outb)
{
    extern __shared__ uint32_t smu[];
    uint32_t* As = smu;              // [64][260]
    uint32_t* Bs = smu + 64*LDK;     // [128][260]
    __shared__ float ob[128];
    const int r0 = blockIdx.x*64;
    const int t = r0 >> 9;
    const int tid = threadIdx.x;
    if (tid < 128) ob[tid] = outb[tid];
#pragma unroll
    for (int q = 0; q < 16; q++){
        int i4 = tid + q*256;        // 0..4095
        int row = i4 >> 6, c4 = i4 & 63;
        int r = r0 + row, b = r & 511;
        float4 v = *(const float4*)&g_H[((t+1)*512 + b)*256 + c4*4];
        uint32_t* d = &As[row*LDK + c4*4];
        d[0]=f2tf(v.x); d[1]=f2tf(v.y); d[2]=f2tf(v.z); d[3]=f2tf(v.w);
    }
#pragma unroll
    for (int q = 0; q < 32; q++){
        int i4 = tid + q*256;        // 0..8191
        int row = i4 >> 6, c4 = i4 & 63;
        float4 v = *(const float4*)&outW[row*256 + c4*4];
        uint32_t* d = &Bs[row*LDK + c4*4];
        d[0]=f2tf(v.x); d[1]=f2tf(v.y); d[2]=f2tf(v.z); d[3]=f2tf(v.w);
    }
    __syncthreads();
    const int wid = tid>>5, lane = tid&31;
    const int wm = wid & 1, wn = wid >> 1;
    const int g = lane>>2, tg = lane&3;
    float acc[2][4][4];
#pragma unroll
    for (int mi=0;mi<2;mi++)
#pragma unroll
        for (int ni=0;ni<4;ni++)
#pragma unroll
            for (int q=0;q<4;q++) acc[mi][ni][q]=0.f;
    const uint32_t* Ab = &As[(wm*32)*LDK];
    const uint32_t* Bb = &Bs[(wn*32)*LDK];
    for (int k0 = 0; k0 < 256; k0 += 8){
        uint32_t a[2][4], b[4][2];
#pragma unroll
        for (int mi=0;mi<2;mi++){
            const uint32_t* p  = Ab + (mi*16+g)*LDK + k0 + tg;
            const uint32_t* p2 = p + 8*LDK;
            a[mi][0]=p[0]; a[mi][2]=p[4]; a[mi][1]=p2[0]; a[mi][3]=p2[4];
        }
#pragma unroll
        for (int ni=0;ni<4;ni++){
            const uint32_t* p = Bb + (ni*8+g)*LDK + k0 + tg;
            b[ni][0]=p[0]; b[ni][1]=p[4];
        }
#pragma unroll
        for (int mi=0;mi<2;mi++)
#pragma unroll
            for (int ni=0;ni<4;ni++)
                mma8(acc[mi][ni], a[mi][0],a[mi][1],a[mi][2],a[mi][3], b[ni][0],b[ni][1]);
    }
    float local = 0.f;
#pragma unroll
    for (int mi=0;mi<2;mi++){
        int r = r0 + wm*32 + mi*16 + g;
        int b = r & 511;
        const float* vr = &values[(b*TT + (t+1))*FF];
        const float* mr = &masks [(b*TT + (t+1))*FF];
        const float* vr8 = &values[((b+8 <= 511 ? ((r+8)&511) : ((r+8)&511))*TT + (t+1))*FF]; // r+8 same t
        const float* mr8 = &masks [(((r+8)&511)*TT + (t+1))*FF];
#pragma unroll
        for (int ni=0;ni<4;ni++){
            int f = wn*32 + ni*8 + 2*tg;
            float o0 = acc[mi][ni][0] + ob[f];
            float o1 = acc[mi][ni][1] + ob[f+1];
            local += fabsf(vr[f]   - o0) * mr[f];
            local += fabsf(vr[f+1] - o1) * mr[f+1];
            float o2 = acc[mi][ni][2] + ob[f];
            float o3 = acc[mi][ni][3] + ob[f+1];
            local += fabsf(vr8[f]   - o2) * mr8[f];
            local += fabsf(vr8[f+1] - o3) * mr8[f+1];
        }
    }
    local *= g_invden[t];
    __syncthreads();                 // smem no longer needed; reuse for reduction
    float* red = (float*)smu;
    red[tid] = local;
    __syncthreads();
    for (int off = 128; off > 0; off >>= 1){
        if (tid < off) red[tid] += red[tid+off];
        __syncthreads();
    }
    if (tid == 0) atomicAdd(&g_loss, (double)red[0]);
}

// ---------------- gather outputs: [h_final | c_final | loss] ----------------
__global__ void k_final(float* __restrict__ out)
{
    int i = blockIdx.x*256 + threadIdx.x;
    if (i < BB*HH)            out[i] = g_H[NS*BB*HH + i];
    else if (i < 2*BB*HH)     out[i] = g_c[i - BB*HH];
    else if (i == 2*BB*HH)    out[i] = (float)g_loss;
}

// ---------------- launch ----------------
extern "C" void kernel_launch(void* const* d_in, const int* in_sizes, int n_in,
                              void* d_out, int out_size)
{
    const float* values = (const float*)d_in[0];
    const float* masks  = (const float*)d_in[1];
    const float* deltas = (const float*)d_in[2];
    const float* featW  = (const float*)d_in[3];
    const float* featb  = (const float*)d_in[4];
    const float* tempW  = (const float*)d_in[5];
    const float* tempb  = (const float*)d_in[6];
    const float* decayW = (const float*)d_in[7];
    const float* decayb = (const float*)d_in[8];
    const float* Wih    = (const float*)d_in[9];
    const float* Whh    = (const float*)d_in[10];
    const float* bih    = (const float*)d_in[11];
    const float* bhh    = (const float*)d_in[12];
    const float* outW   = (const float*)d_in[13];
    const float* outb   = (const float*)d_in[14];

    const int SM_VHAT  = 3*128*132*4;          // 202752
    const int SM_GAMMA = (128+64)*LDK1*4;      // 101376
    const int SM_ZX    = (128+64)*LDK*4;       // 199680
    const int SM_STEP  = (32+64)*LDK*4;        //  99840
    const int SM_LOSS  = (64+128)*LDK*4;       // 199680

    cudaFuncSetAttribute(k_vhat,     cudaFuncAttributeMaxDynamicSharedMemorySize, SM_VHAT);
    cudaFuncSetAttribute(k_gamma_tc, cudaFuncAttributeMaxDynamicSharedMemorySize, SM_GAMMA);
    cudaFuncSetAttribute(k_zx_tc,    cudaFuncAttributeMaxDynamicSharedMemorySize, SM_ZX);
    cudaFuncSetAttribute(k_step_tc,  cudaFuncAttributeMaxDynamicSharedMemorySize, SM_STEP);
    cudaFuncSetAttribute(k_loss_tc,  cudaFuncAttributeMaxDynamicSharedMemorySize, SM_LOSS);

    k_init<<<512, 256>>>();
    k_invden<<<NS, 256>>>(masks);
    k_vhat<<<BB, 256, SM_VHAT>>>(values, masks, featW, featb, tempW, tempb);
    k_gamma_tc<<<dim3(BB*TT/128, HH/64), 256, SM_GAMMA>>>(deltas, decayW, decayb);
    k_zx_tc<<<dim3(NS*BB/128, 4*HH/64), 256, SM_ZX>>>(masks, Wih, bih, bhh);
    for (int t = 0; t < NS; t++)
        k_step_tc<<<dim3(16, 16), 128, SM_STEP>>>(Whh, t);
    k_loss_tc<<<NS*BB/64, 256, SM_LOSS>>>(values, masks, outW, outb);
    k_final<<<(2*BB*HH + 1 + 255)/256, 256>>>((float*)d_out);
}

// round 17
// speedup vs baseline: 1.7850x; 1.0083x over previous
#include <cuda_runtime.h>
#include <math.h>
#include <stdint.h>

#define BB 512
#define TT 128
#define FF 128
#define HH 256
#define NS 127   // T-1 scan steps

// ---------------- scratch (static device memory; no allocations) ----------------
__device__ float g_vhat[BB*TT*FF];            // values_hat           [b][t][f]
__device__ float g_gamma[BB*TT*HH];           // gamma                [b*T+t][h]
__device__ float g_zx[NS*BB*4*HH];            // input-gate preact    [t][b][n]
__device__ float g_H[(NS+1)*BB*HH];           // h history, slot0=h0  [t][b][h]
__device__ float g_c[BB*HH];                  // cell state
__device__ float g_invden[NS];
__device__ double g_loss;

__device__ __forceinline__ float sigf(float x){ return 1.f/(1.f+expf(-x)); }

__device__ __forceinline__ uint32_t f2tf(float x){
    uint32_t r; asm("cvt.rna.tf32.f32 %0, %1;" : "=r"(r) : "f"(x)); return r;
}
// D += A(16x8,row) * B(8x8,col), tf32 in, fp32 accum
__device__ __forceinline__ void mma8(float* d,
    uint32_t a0, uint32_t a1, uint32_t a2, uint32_t a3,
    uint32_t b0, uint32_t b1)
{
    asm volatile("mma.sync.aligned.m16n8k8.row.col.f32.tf32.tf32.f32 "
        "{%0,%1,%2,%3}, {%4,%5,%6,%7}, {%8,%9}, {%0,%1,%2,%3};"
        : "+f"(d[0]), "+f"(d[1]), "+f"(d[2]), "+f"(d[3])
        : "r"(a0), "r"(a1), "r"(a2), "r"(a3), "r"(b0), "r"(b1));
}

#define LDK 260   // K=256 pad  (260 % 32 == 4 -> conflict-free fragment LDS)
#define LDK1 132  // K=128 pad

// ---------------- init: h0 = c0 = 0, loss = 0 ----------------
__global__ void k_init()
{
    int i = blockIdx.x*256 + threadIdx.x;
    if (i < BB*HH){ g_c[i] = 0.f; g_H[i] = 0.f; }
    if (i == 0) g_loss = 0.0;
}

// ---------------- per-step loss denominators: 1/(sum(masks[:,t+1])+1e-5) ----------------
__global__ void k_invden(const float* __restrict__ masks)
{
    int t = blockIdx.x;              // 0..126, uses masks at time t+1
    float s = 0.f;
    for (int i = threadIdx.x; i < BB*FF; i += 256){
        int b = i >> 7, f = i & 127;
        s += masks[(b*TT + (t+1))*FF + f];
    }
    __shared__ float red[256];
    red[threadIdx.x] = s; __syncthreads();
    for (int off = 128; off > 0; off >>= 1){
        if (threadIdx.x < off) red[threadIdx.x] += red[threadIdx.x+off];
        __syncthreads();
    }
    if (threadIdx.x == 0) g_invden[t] = 1.f/(red[0] + 1e-5f);
}

// ---------------- values_hat: feature + temporal regression fused (exact fp32) ----------------
__global__ __launch_bounds__(256) void k_vhat(
    const float* __restrict__ values, const float* __restrict__ masks,
    const float* __restrict__ featW,  const float* __restrict__ featb,
    const float* __restrict__ tempW,  const float* __restrict__ tempb)
{
    extern __shared__ float sm[];
    float* Vs = sm;                // [128][132]
    float* Wf = sm + 128*132;      // [128][132]
    float* Wt = sm + 2*128*132;    // [128][132]
    const int b = blockIdx.x, tid = threadIdx.x;
    const float4* v4 = (const float4*)(values + b*TT*FF);
    const float4* f4 = (const float4*)featW;
    const float4* t4 = (const float4*)tempW;
#pragma unroll
    for (int q = 0; q < 16; q++){
        int i4 = tid + q*256;
        int row = i4 >> 5, c4 = i4 & 31;
        *(float4*)&Vs[row*132 + c4*4] = v4[i4];
        *(float4*)&Wf[row*132 + c4*4] = f4[i4];
        *(float4*)&Wt[row*132 + c4*4] = t4[i4];
    }
    __syncthreads();
    const int tx = tid & 15, ty = tid >> 4;
    float acc[8][8];
#pragma unroll
    for (int i=0;i<8;i++)
#pragma unroll
        for (int j=0;j<8;j++) acc[i][j] = 0.f;

    for (int k0 = 0; k0 < 128; k0 += 4){
        float4 a[8], w[8];
#pragma unroll
        for (int i=0;i<8;i++) a[i] = *(const float4*)&Vs[(ty+16*i)*132 + k0];
#pragma unroll
        for (int j=0;j<8;j++) w[j] = *(const float4*)&Wf[(tx+16*j)*132 + k0];
#pragma unroll
        for (int i=0;i<8;i++)
#pragma unroll
            for (int j=0;j<8;j++)
                acc[i][j] += a[i].x*w[j].x + a[i].y*w[j].y + a[i].z*w[j].z + a[i].w*w[j].w;
    }
    for (int k0 = 0; k0 < 128; k0 += 4){
        float4 a[8];
#pragma unroll
        for (int i=0;i<8;i++) a[i] = *(const float4*)&Wt[(ty+16*i)*132 + k0];
#pragma unroll
        for (int kk=0;kk<4;kk++){
            float vg[8];
#pragma unroll
            for (int j=0;j<8;j++) vg[j] = Vs[(k0+kk)*132 + tx + 16*j];
#pragma unroll
            for (int i=0;i<8;i++){
                float av = (kk==0)?a[i].x:(kk==1)?a[i].y:(kk==2)?a[i].z:a[i].w;
#pragma unroll
                for (int j=0;j<8;j++) acc[i][j] += av * vg[j];
            }
        }
    }
    const float* mrow = masks + b*TT*FF;
#pragma unroll
    for (int i=0;i<8;i++){
        int t = ty + 16*i;
        float tb  = tempb[t];
        float wtd = Wt[t*132 + t];
#pragma unroll
        for (int j=0;j<8;j++){
            int g = tx + 16*j;
            float v  = Vs[t*132 + g];
            float vh = acc[i][j] - v*(Wf[g*132 + g] + wtd) + featb[g] + tb;
            float m  = mrow[t*FF + g];
            g_vhat[(b*TT + t)*FF + g] = v*m + vh*(1.f - m);
        }
    }
}

// ---------------- gamma = exp(-|deltas @ decay_W^T + b|)  (TF32 mma) ----------------
// tile 128 rows x 64 h, K=128 resident; 8 warps of 32x32 (wm 0..3, wn 0..1)
__global__ __launch_bounds__(256) void k_gamma_tc(
    const float* __restrict__ deltas, const float* __restrict__ decayW,
    const float* __restrict__ decayb)
{
    extern __shared__ uint32_t smu[];
    uint32_t* As = smu;               // [128][132]
    uint32_t* Bs = smu + 128*LDK1;    // [64][132]
    __shared__ float db[64];
    const int r0 = blockIdx.x*128, h0 = blockIdx.y*64, tid = threadIdx.x;
    if (tid < 64) db[tid] = decayb[h0 + tid];
#pragma unroll
    for (int q=0;q<16;q++){
        int i4 = tid + q*256;                // 0..4095
        int row = i4 >> 5, c4 = i4 & 31;
        float4 v = *(const float4*)&deltas[(r0+row)*FF + c4*4];
        uint32_t* d = &As[row*LDK1 + c4*4];
        d[0]=f2tf(v.x); d[1]=f2tf(v.y); d[2]=f2tf(v.z); d[3]=f2tf(v.w);
    }
#pragma unroll
    for (int q=0;q<8;q++){
        int i4 = tid + q*256;                // 0..2047
        int row = i4 >> 5, c4 = i4 & 31;
        float4 v = *(const float4*)&decayW[(h0+row)*FF + c4*4];
        uint32_t* d = &Bs[row*LDK1 + c4*4];
        d[0]=f2tf(v.x); d[1]=f2tf(v.y); d[2]=f2tf(v.z); d[3]=f2tf(v.w);
    }
    __syncthreads();
    const int wid = tid>>5, lane = tid&31;
    const int wm = wid & 3, wn = wid >> 2;
    const int g = lane>>2, tg = lane&3;
    float acc[2][4][4];
#pragma unroll
    for (int mi=0;mi<2;mi++)
#pragma unroll
        for (int ni=0;ni<4;ni++)
#pragma unroll
            for (int q=0;q<4;q++) acc[mi][ni][q]=0.f;
    const uint32_t* Ab = &As[(wm*32)*LDK1];
    const uint32_t* Bb = &Bs[(wn*32)*LDK1];
    for (int k0=0;k0<128;k0+=8){
        uint32_t a[2][4], b[4][2];
#pragma unroll
        for (int mi=0;mi<2;mi++){
            const uint32_t* p  = Ab + (mi*16+g)*LDK1 + k0 + tg;
            const uint32_t* p2 = p + 8*LDK1;
            a[mi][0]=p[0]; a[mi][2]=p[4]; a[mi][1]=p2[0]; a[mi][3]=p2[4];
        }
#pragma unroll
        for (int ni=0;ni<4;ni++){
            const uint32_t* p = Bb + (ni*8+g)*LDK1 + k0 + tg;
            b[ni][0]=p[0]; b[ni][1]=p[4];
        }
#pragma unroll
        for (int mi=0;mi<2;mi++)
#pragma unroll
            for (int ni=0;ni<4;ni++)
                mma8(acc[mi][ni], a[mi][0],a[mi][1],a[mi][2],a[mi][3], b[ni][0],b[ni][1]);
    }
#pragma unroll
    for (int mi=0;mi<2;mi++){
        int r = r0 + wm*32 + mi*16 + g;
#pragma unroll
        for (int ni=0;ni<4;ni++){
            int nl = wn*32 + ni*8 + 2*tg;
            float2 v0 = { expf(-fabsf(acc[mi][ni][0] + db[nl])),
                          expf(-fabsf(acc[mi][ni][1] + db[nl+1])) };
            *(float2*)&g_gamma[r*HH + h0 + nl] = v0;
            float2 v1 = { expf(-fabsf(acc[mi][ni][2] + db[nl])),
                          expf(-fabsf(acc[mi][ni][3] + db[nl+1])) };
            *(float2*)&g_gamma[(r+8)*HH + h0 + nl] = v1;
        }
    }
}

// ---------------- zx = [values_hat, masks] @ W_ih^T + b_ih + b_hh  (TF32 mma) ----------------
// M=65024 (r=t*512+b), N=1024, K=256; block tile 128x64, 8 warps of 32x32 (wm 0..3, wn 0..1)
__global__ __launch_bounds__(256) void k_zx_tc(
    const float* __restrict__ masks, const float* __restrict__ Wih,
    const float* __restrict__ bih,   const float* __restrict__ bhh)
{
    extern __shared__ uint32_t smu[];
    uint32_t* As = smu;              // [128][260]
    uint32_t* Bs = smu + 128*LDK;    // [64][260]
    __shared__ float bb[64];
    const int r0 = blockIdx.x*128, n0 = blockIdx.y*64, tid = threadIdx.x;
    if (tid < 64) bb[tid] = bih[n0+tid] + bhh[n0+tid];
#pragma unroll
    for (int q = 0; q < 32; q++){
        int i4 = tid + q*256;        // 0..8191
        int row = i4 >> 6, c4 = i4 & 63;
        int r = r0 + row, t = r >> 9, b = r & 511;
        int k = c4*4;
        const float* src = (k < 128) ? &g_vhat[(b*TT+t)*FF + k]
                                     : &masks[(b*TT+t)*FF + (k-128)];
        float4 v = *(const float4*)src;
        uint32_t* d = &As[row*LDK + k];
        d[0]=f2tf(v.x); d[1]=f2tf(v.y); d[2]=f2tf(v.z); d[3]=f2tf(v.w);
    }
#pragma unroll
    for (int q = 0; q < 16; q++){
        int i4 = tid + q*256;        // 0..4095
        int row = i4 >> 6, c4 = i4 & 63;
        float4 v = *(const float4*)&Wih[(n0+row)*256 + c4*4];
        uint32_t* d = &Bs[row*LDK + c4*4];
        d[0]=f2tf(v.x); d[1]=f2tf(v.y); d[2]=f2tf(v.z); d[3]=f2tf(v.w);
    }
    __syncthreads();
    const int wid = tid>>5, lane = tid&31;
    const int wm = wid & 3, wn = wid >> 2;
    const int g = lane>>2, tg = lane&3;
    float acc[2][4][4];
#pragma unroll
    for (int mi=0;mi<2;mi++)
#pragma unroll
        for (int ni=0;ni<4;ni++)
#pragma unroll
            for (int q=0;q<4;q++) acc[mi][ni][q]=0.f;
    const uint32_t* Ab = &As[(wm*32)*LDK];
    const uint32_t* Bb = &Bs[(wn*32)*LDK];
    for (int k0 = 0; k0 < 256; k0 += 8){
        uint32_t a[2][4], b[4][2];
#pragma unroll
        for (int mi=0;mi<2;mi++){
            const uint32_t* p  = Ab + (mi*16+g)*LDK + k0 + tg;
            const uint32_t* p2 = p + 8*LDK;
            a[mi][0]=p[0]; a[mi][2]=p[4]; a[mi][1]=p2[0]; a[mi][3]=p2[4];
        }
#pragma unroll
        for (int ni=0;ni<4;ni++){
            const uint32_t* p = Bb + (ni*8+g)*LDK + k0 + tg;
            b[ni][0]=p[0]; b[ni][1]=p[4];
        }
#pragma unroll
        for (int mi=0;mi<2;mi++)
#pragma unroll
            for (int ni=0;ni<4;ni++)
                mma8(acc[mi][ni], a[mi][0],a[mi][1],a[mi][2],a[mi][3], b[ni][0],b[ni][1]);
    }
#pragma unroll
    for (int mi=0;mi<2;mi++){
        int r = r0 + wm*32 + mi*16 + g;
#pragma unroll
        for (int ni=0;ni<4;ni++){
            int nl = wn*32 + ni*8 + 2*tg;
            float2 v0 = { acc[mi][ni][0] + bb[nl], acc[mi][ni][1] + bb[nl+1] };
            *(float2*)&g_zx[r*1024 + n0 + nl] = v0;
            float2 v1 = { acc[mi][ni][2] + bb[nl], acc[mi][ni][3] + bb[nl+1] };
            *(float2*)&g_zx[(r+8)*1024 + n0 + nl] = v1;
        }
    }
}

// ---------------- one LSTM scan step (TF32 mma) ----------------
// block tile 32(b) x 64(n = 4 gates x 16 j); 4 warps, warp wn owns gate wn (32x16).
// grid (16,16)=256 blocks, 128 threads.
__global__ __launch_bounds__(128) void k_step_tc(const float* __restrict__ Whh, int t)
{
    extern __shared__ uint32_t smu[];
    uint32_t* As = smu;             // [32][260]  decayed h (tf32)
    uint32_t* Bs = smu + 32*LDK;    // [64][260]  Whh rows: 4 gates x 16 j
    const int b0 = blockIdx.x*32, j0 = blockIdx.y*16, tid = threadIdx.x;
#pragma unroll
    for (int q = 0; q < 16; q++){
        int i4 = tid + q*128;        // 0..2047
        int row = i4 >> 6, c4 = i4 & 63;
        int b = b0 + row;
        float4 hv = *(const float4*)&g_H[(t*512 + b)*256 + c4*4];
        float4 gv = *(const float4*)&g_gamma[(b*TT + t)*HH + c4*4];
        uint32_t* d = &As[row*LDK + c4*4];
        d[0]=f2tf(hv.x*gv.x); d[1]=f2tf(hv.y*gv.y);
        d[2]=f2tf(hv.z*gv.z); d[3]=f2tf(hv.w*gv.w);
    }
#pragma unroll
    for (int q = 0; q < 32; q++){
        int i4 = tid + q*128;        // 0..4095
        int row = i4 >> 6, c4 = i4 & 63;
        int gate = row >> 4, jj = row & 15;
        float4 v = *(const float4*)&Whh[(gate*256 + j0 + jj)*256 + c4*4];
        uint32_t* d = &Bs[row*LDK + c4*4];
        d[0]=f2tf(v.x); d[1]=f2tf(v.y); d[2]=f2tf(v.z); d[3]=f2tf(v.w);
    }
    __syncthreads();
    const int wid = tid>>5, lane = tid&31;
    const int wn = wid;              // gate index
    const int g = lane>>2, tg = lane&3;
    float acc[2][2][4];
#pragma unroll
    for (int mi=0;mi<2;mi++)
#pragma unroll
        for (int ni=0;ni<2;ni++)
#pragma unroll
            for (int q=0;q<4;q++) acc[mi][ni][q]=0.f;
    const uint32_t* Bb = &Bs[(wn*16)*LDK];
    for (int k0 = 0; k0 < 256; k0 += 8){
        uint32_t a[2][4], b[2][2];
#pragma unroll
        for (int mi=0;mi<2;mi++){
            const uint32_t* p  = &As[(mi*16+g)*LDK + k0 + tg];
            const uint32_t* p2 = p + 8*LDK;
            a[mi][0]=p[0]; a[mi][2]=p[4]; a[mi][1]=p2[0]; a[mi][3]=p2[4];
        }
#pragma unroll
        for (int ni=0;ni<2;ni++){
            const uint32_t* p = Bb + (ni*8+g)*LDK + k0 + tg;
            b[ni][0]=p[0]; b[ni][1]=p[4];
        }
#pragma unroll
        for (int mi=0;mi<2;mi++)
#pragma unroll
            for (int ni=0;ni<2;ni++)
                mma8(acc[mi][ni], a[mi][0],a[mi][1],a[mi][2],a[mi][3], b[ni][0],b[ni][1]);
    }
    __syncthreads();                     // everyone done reading As/Bs
    float* Zs = (float*)smu;             // reuse As region: [32][260] floats
#pragma unroll
    for (int mi=0;mi<2;mi++){
        int rr = mi*16 + g;
#pragma unroll
        for (int ni=0;ni<2;ni++){
            int cc = wn*16 + ni*8 + 2*tg;
            Zs[rr*LDK + cc]     = acc[mi][ni][0];
            Zs[rr*LDK + cc + 1] = acc[mi][ni][1];
            Zs[(rr+8)*LDK + cc]     = acc[mi][ni][2];
            Zs[(rr+8)*LDK + cc + 1] = acc[mi][ni][3];
        }
    }
    __syncthreads();
    // gate fusion: 32 b x 16 j = 512 pairs / 128 threads
#pragma unroll
    for (int q = 0; q < 4; q++){
        int idx = tid + q*128;       // 0..511
        int bl = idx >> 4, jj = idx & 15;
        int b = b0 + bl, j = j0 + jj;
        const float* zr = g_zx + (t*512 + b)*1024;
        float zi = Zs[bl*LDK + 0*16 + jj] + zr[j];
        float zf = Zs[bl*LDK + 1*16 + jj] + zr[256 + j];
        float zg = Zs[bl*LDK + 2*16 + jj] + zr[512 + j];
        float zo = Zs[bl*LDK + 3*16 + jj] + zr[768 + j];
        float ii = sigf(zi), ff = sigf(zf), gg = tanhf(zg), oo = sigf(zo);
        float c = ff * g_c[b*256 + j] + ii*gg;
        g_c[b*256 + j] = c;
        g_H[((t+1)*512 + b)*256 + j] = oo * tanhf(c);
    }
}

// ---------------- output projection + masked L1 loss (TF32 mma) ----------------
// block tile 64(r, within one t) x 128(f); 8 warps of 32x32 (wm 0..1, wn 0..3)
__global__ __launch_bounds__(256) void k_loss_tc(
    const float* __restrict__ values, const float* __restrict__ masks,
    const float* __restrict__ outW,   const float* __restrict__ outb)
{
    extern __shared__ uint32_t smu[];
    uint32_t* As = smu;              // [64][260]
    uint32_t* Bs = smu + 64*LDK;     // [128][260]
    __shared__ float ob[128];
    const int r0 = blockIdx.x*64;
    const int t = r0 >> 9;
    const int tid = threadIdx.x;
    if (tid < 128) ob[tid] = outb[tid];
#pragma unroll
    for (int q = 0; q < 16; q++){
        int i4 = tid + q*256;        // 0..4095
        int row = i4 >> 6, c4 = i4 & 63;
        int r = r0 + row, b = r & 511;
        float4 v = *(const float4*)&g_H[((t+1)*512 + b)*256 + c4*4];
        uint32_t* d = &As[row*LDK + c4*4];
        d[0]=f2tf(v.x); d[1]=f2tf(v.y); d[2]=f2tf(v.z); d[3]=f2tf(v.w);
    }
#pragma unroll
    for (int q = 0; q < 32; q++){
        int i4 = tid + q*256;        // 0..8191
        int row = i4 >> 6, c4 = i4 & 63;
        float4 v = *(const float4*)&outW[row*256 + c4*4];
        uint32_t* d = &Bs[row*LDK + c4*4];
        d[0]=f2tf(v.x); d[1]=f2tf(v.y); d[2]=f2tf(v.z); d[3]=f2tf(v.w);
    }
    __syncthreads();
    const int wid = tid>>5, lane = tid&31;
    const int wm = wid & 1, wn = wid >> 1;
    const int g = lane>>2, tg = lane&3;
    float acc[2][4][4];
#pragma unroll
    for (int mi=0;mi<2;mi++)
#pragma unroll
        for (int ni=0;ni<4;ni++)
#pragma unroll
            for (int q=0;q<4;q++) acc[mi][ni][q]=0.f;
    const uint32_t* Ab = &As[(wm*32)*LDK];
    const uint32_t* Bb = &Bs[(wn*32)*LDK];
    for (int k0 = 0; k0 < 256; k0 += 8){
        uint32_t a[2][4], b[4][2];
#pragma unroll
        for (int mi=0;mi<2;mi++){
            const uint32_t* p  = Ab + (mi*16+g)*LDK + k0 + tg;
            const uint32_t* p2 = p + 8*LDK;
            a[mi][0]=p[0]; a[mi][2]=p[4]; a[mi][1]=p2[0]; a[mi][3]=p2[4];
        }
#pragma unroll
        for (int ni=0;ni<4;ni++){
            const uint32_t* p = Bb + (ni*8+g)*LDK + k0 + tg;
            b[ni][0]=p[0]; b[ni][1]=p[4];
        }
#pragma unroll
        for (int mi=0;mi<2;mi++)
#pragma unroll
            for (int ni=0;ni<4;ni++)
                mma8(acc[mi][ni], a[mi][0],a[mi][1],a[mi][2],a[mi][3], b[ni][0],b[ni][1]);
    }
    float local = 0.f;
#pragma unroll
    for (int mi=0;mi<2;mi++){
        int r = r0 + wm*32 + mi*16 + g;
        int b = r & 511;
        const float* vr = &values[(b*TT + (t+1))*FF];
        const float* mr = &masks [(b*TT + (t+1))*FF];
        const float* vr8 = &values[((b+8 <= 511 ? ((r+8)&511) : ((r+8)&511))*TT + (t+1))*FF]; // r+8 same t
        const float* mr8 = &masks [(((r+8)&511)*TT + (t+1))*FF];
#pragma unroll
        for (int ni=0;ni<4;ni++){
            int f = wn*32 + ni*8 + 2*tg;
            float o0 = acc[mi][ni][0] + ob[f];
            float o1 = acc[mi][ni][1] + ob[f+1];
            local += fabsf(vr[f]   - o0) * mr[f];
            local += fabsf(vr[f+1] - o1) * mr[f+1];
            float o2 = acc[mi][ni][2] + ob[f];
            float o3 = acc[mi][ni][3] + ob[f+1];
            local += fabsf(vr8[f]   - o2) * mr8[f];
            local += fabsf(vr8[f+1] - o3) * mr8[f+1];
        }
    }
    local *= g_invden[t];
    __syncthreads();                 // smem no longer needed; reuse for reduction
    float* red = (float*)smu;
    red[tid] = local;
    __syncthreads();
    for (int off = 128; off > 0; off >>= 1){
        if (tid < off) red[tid] += red[tid+off];
        __syncthreads();
    }
    if (tid == 0) atomicAdd(&g_loss, (double)red[0]);
}

// ---------------- gather outputs: [h_final | c_final | loss] ----------------
__global__ void k_final(float* __restrict__ out)
{
    int i = blockIdx.x*256 + threadIdx.x;
    if (i < BB*HH)            out[i] = g_H[NS*BB*HH + i];
    else if (i < 2*BB*HH)     out[i] = g_c[i - BB*HH];
    else if (i == 2*BB*HH)    out[i] = (float)g_loss;
}

// ---------------- launch ----------------
extern "C" void kernel_launch(void* const* d_in, const int* in_sizes, int n_in,
                              void* d_out, int out_size)
{
    const float* values = (const float*)d_in[0];
    const float* masks  = (const float*)d_in[1];
    const float* deltas = (const float*)d_in[2];
    const float* featW  = (const float*)d_in[3];
    const float* featb  = (const float*)d_in[4];
    const float* tempW  = (const float*)d_in[5];
    const float* tempb  = (const float*)d_in[6];
    const float* decayW = (const float*)d_in[7];
    const float* decayb = (const float*)d_in[8];
    const float* Wih    = (const float*)d_in[9];
    const float* Whh    = (const float*)d_in[10];
    const float* bih    = (const float*)d_in[11];
    const float* bhh    = (const float*)d_in[12];
    const float* outW   = (const float*)d_in[13];
    const float* outb   = (const float*)d_in[14];

    const int SM_VHAT  = 3*128*132*4;          // 202752
    const int SM_GAMMA = (128+64)*LDK1*4;      // 101376
    const int SM_ZX    = (128+64)*LDK*4;       // 199680
    const int SM_STEP  = (32+64)*LDK*4;        //  99840
    const int SM_LOSS  = (64+128)*LDK*4;       // 199680

    cudaFuncSetAttribute(k_vhat,     cudaFuncAttributeMaxDynamicSharedMemorySize, SM_VHAT);
    cudaFuncSetAttribute(k_gamma_tc, cudaFuncAttributeMaxDynamicSharedMemorySize, SM_GAMMA);
    cudaFuncSetAttribute(k_zx_tc,    cudaFuncAttributeMaxDynamicSharedMemorySize, SM_ZX);
    cudaFuncSetAttribute(k_step_tc,  cudaFuncAttributeMaxDynamicSharedMemorySize, SM_STEP);
    cudaFuncSetAttribute(k_loss_tc,  cudaFuncAttributeMaxDynamicSharedMemorySize, SM_LOSS);

    k_init<<<512, 256>>>();
    k_invden<<<NS, 256>>>(masks);
    k_vhat<<<BB, 256, SM_VHAT>>>(values, masks, featW, featb, tempW, tempb);
    k_gamma_tc<<<dim3(BB*TT/128, HH/64), 256, SM_GAMMA>>>(deltas, decayW, decayb);
    k_zx_tc<<<dim3(NS*BB/128, 4*HH/64), 256, SM_ZX>>>(masks, Wih, bih, bhh);
    for (int t = 0; t < NS; t++)
        k_step_tc<<<dim3(16, 16), 128, SM_STEP>>>(Whh, t);
    k_loss_tc<<<NS*BB/64, 256, SM_LOSS>>>(values, masks, outW, outb);
    k_final<<<(2*BB*HH + 1 + 255)/256, 256>>>((float*)d_out);
}